// round 14
// baseline (speedup 1.0000x reference)
#include <cuda_runtime.h>
#include <cuda_fp16.h>
#include <cstdint>

#define B_  4
#define N_  2048
#define M_  2048
#define H_  16
#define D_  64
#define E_  1024
#define R_  8192   // B_*N_

// fp16 tensors
__device__ __half g_Q[(size_t)B_ * H_ * N_ * D_];   // pre-scaled (scale*log2e folded into Wq)
__device__ __half g_K[(size_t)B_ * H_ * M_ * D_];
__device__ __half g_V[(size_t)B_ * H_ * M_ * D_];
__device__ __half g_Xh[(size_t)R_ * E_];
__device__ __half g_Ch[(size_t)R_ * E_];
__device__ __half g_AO[(size_t)R_ * E_];
__device__ __half g_W4[(size_t)4 * E_ * E_];

// ---------------------------------------------------------------------------
// helpers
// ---------------------------------------------------------------------------
__device__ __forceinline__ void mma16h(float* d, const unsigned* a, unsigned b0, unsigned b1) {
    asm("mma.sync.aligned.m16n8k16.row.col.f32.f16.f16.f32 "
        "{%0,%1,%2,%3},{%4,%5,%6,%7},{%8,%9},{%0,%1,%2,%3};"
        : "+f"(d[0]), "+f"(d[1]), "+f"(d[2]), "+f"(d[3])
        : "r"(a[0]), "r"(a[1]), "r"(a[2]), "r"(a[3]), "r"(b0), "r"(b1));
}
__device__ __forceinline__ unsigned packh(float lo, float hi) {
    unsigned r; asm("cvt.rn.f16x2.f32 %0, %1, %2;" : "=r"(r) : "f"(hi), "f"(lo)); return r;
}
__device__ __forceinline__ unsigned h2ex2(unsigned x) {
    unsigned y; asm("ex2.approx.f16x2 %0, %1;" : "=r"(y) : "r"(x)); return y;
}
__device__ __forceinline__ void ldsm4(unsigned* r, unsigned addr) {
    asm volatile("ldmatrix.sync.aligned.m8n8.x4.shared.b16 {%0,%1,%2,%3}, [%4];"
                 : "=r"(r[0]), "=r"(r[1]), "=r"(r[2]), "=r"(r[3]) : "r"(addr));
}
__device__ __forceinline__ void ldsm4t(unsigned* r, unsigned addr) {
    asm volatile("ldmatrix.sync.aligned.m8n8.x4.trans.shared.b16 {%0,%1,%2,%3}, [%4];"
                 : "=r"(r[0]), "=r"(r[1]), "=r"(r[2]), "=r"(r[3]) : "r"(addr));
}
__device__ __forceinline__ void cpa16(unsigned dst, const void* src) {
    asm volatile("cp.async.cg.shared.global [%0], [%1], 16;" :: "r"(dst), "l"(src));
}
__device__ __forceinline__ void cpacommit() { asm volatile("cp.async.commit_group;"); }
__device__ __forceinline__ void cpawait0()  { asm volatile("cp.async.wait_group 0;"); }
__device__ __forceinline__ void cpawait1()  { asm volatile("cp.async.wait_group 1;"); }
__device__ __forceinline__ void cpawait2()  { asm volatile("cp.async.wait_group 2;"); }
__device__ __forceinline__ unsigned smem_u32(const void* p) {
    unsigned a;
    asm("{ .reg .u64 t; cvta.to.shared.u64 t, %1; cvt.u32.u64 %0, t; }" : "=r"(a) : "l"(p));
    return a;
}
#define ONESH2 0x3C003C00u   // fp16x2 {1.0, 1.0}

// ---------------------------------------------------------------------------
// Prep: fp32 -> fp16 converts (x+ctx fused; 4 weights fused)
// ---------------------------------------------------------------------------
__global__ __launch_bounds__(256) void f2h2(
    const float* __restrict__ x, const float* __restrict__ ctx,
    __half* __restrict__ Xh, __half* __restrict__ Ch, int n4)
{
    int i = blockIdx.x * 256 + threadIdx.x;
    const float* s; __half* d; int j;
    if (i < n4) { s = x; d = Xh; j = i; } else { s = ctx; d = Ch; j = i - n4; }
    float4 v = ((const float4*)s)[j];
    __half2 a = __floats2half2_rn(v.x, v.y);
    __half2 b = __floats2half2_rn(v.z, v.w);
    uint2 u; u.x = *(unsigned*)&a; u.y = *(unsigned*)&b;
    *(uint2*)&d[(size_t)j * 4] = u;
}
__global__ __launch_bounds__(256) void f2hw(
    const float* __restrict__ w0, const float* __restrict__ w1,
    const float* __restrict__ w2, const float* __restrict__ w3,
    __half* __restrict__ dst, float qs)
{
    int i = blockIdx.x * 256 + threadIdx.x;
    const int per = E_ * E_ / 4;
    int s = i / per, j = i - s * per;
    const float* src = (s == 0) ? w0 : (s == 1) ? w1 : (s == 2) ? w2 : w3;
    float scale = (s == 0) ? qs : 1.f;
    float4 v = ((const float4*)src)[j];
    __half2 a = __floats2half2_rn(v.x * scale, v.y * scale);
    __half2 b = __floats2half2_rn(v.z * scale, v.w * scale);
    uint2 u; u.x = *(unsigned*)&a; u.y = *(unsigned*)&b;
    *(uint2*)&dst[(size_t)i * 4] = u;
}

// ---------------------------------------------------------------------------
// fp16 GEMM: Y = A (R x 1024) @ W^T, fp32 accumulate.
// Block 128x128 tile, 8 warps (warp tile 64x32). K-chunks of 32 halves,
// 4-stage cp.async pipeline (80KB dynamic smem), row stride 80B
// (conflict-free ldmatrix: 80r mod 128 covers all 16B groups).
// grid.z selects {A, W, Y} (fused projections); mode 1 = fp32+bias out.
// ---------------------------------------------------------------------------
#define GROW 80u
#define GST  20480u    // (128*80)*2 bytes per stage (A then B)
#define GSM  (4 * 20480)

__global__ __launch_bounds__(256) void gemm_h(
    const __half* __restrict__ A0, const __half* __restrict__ A1,
    const __half* __restrict__ Wb, int wofs,
    float* __restrict__ Yf, __half* __restrict__ Y0, __half* __restrict__ Y1,
    __half* __restrict__ Y2, const float* __restrict__ bias, int mode)
{
    extern __shared__ char sm[];
    const int z = blockIdx.z;
    const __half* A = (z == 0) ? A0 : A1;
    const __half* W = Wb + (size_t)(wofs + z) * E_ * E_;
    __half* Yh = (z == 0) ? Y0 : (z == 1) ? Y1 : Y2;

    const int tid = threadIdx.x, lane = tid & 31, warp = tid >> 5;
    const int g = lane >> 2, tg = lane & 3;
    const int wm = (warp >> 2) * 64, wn = (warp & 3) * 32;
    const int m0 = blockIdx.y * 128, n0 = blockIdx.x * 128;

    const unsigned asB = smem_u32(sm);
    const unsigned bsB = asB + 10240u;
    const int lrow = ((lane >> 3) & 1) * 8 + (lane & 7);
    const int lkh  = lane >> 4;
    const unsigned aoff = (unsigned)((wm + lrow) * GROW + lkh * 16);
    const unsigned boff = (unsigned)((wn + lrow) * GROW + lkh * 16);

    const int crow = tid >> 1, chalf = tid & 1;
    const __half* Asrc = A + (size_t)(m0 + crow) * E_ + chalf * 16;
    const __half* Bsrc = W + (size_t)(n0 + crow) * E_ + chalf * 16;
    const unsigned cda = (unsigned)(crow * GROW + chalf * 32);

    auto issue = [&](int c) {
        const unsigned base = (unsigned)(c & 3) * GST;
        cpa16(asB + base + cda,      Asrc + c * 32);
        cpa16(asB + base + cda + 16, Asrc + c * 32 + 8);
        cpa16(bsB + base + cda,      Bsrc + c * 32);
        cpa16(bsB + base + cda + 16, Bsrc + c * 32 + 8);
        cpacommit();
    };

    float acc[4][4][4];
#pragma unroll
    for (int i = 0; i < 4; ++i)
#pragma unroll
        for (int j = 0; j < 4; ++j)
#pragma unroll
            for (int k = 0; k < 4; ++k) acc[i][j][k] = 0.f;

    issue(0); issue(1); issue(2);
    for (int c = 0; c < 32; ++c) {
        if (c <= 29) cpawait2(); else if (c == 30) cpawait1(); else cpawait0();
        __syncthreads();
        if (c + 3 < 32) issue(c + 3);
        const unsigned bufo = (unsigned)(c & 3) * GST;

#pragma unroll
        for (int kh = 0; kh < 2; ++kh) {
            unsigned ah[4][4], bh[2][4];
#pragma unroll
            for (int mt = 0; mt < 4; ++mt)
                ldsm4(ah[mt], asB + bufo + aoff + (unsigned)(kh * 32 + mt * 1280));
#pragma unroll
            for (int p = 0; p < 2; ++p)
                ldsm4(bh[p], bsB + bufo + boff + (unsigned)(kh * 32 + p * 1280));
#pragma unroll
            for (int mt = 0; mt < 4; ++mt)
#pragma unroll
                for (int nt = 0; nt < 4; ++nt) {
                    const int p = nt >> 1, sel = nt & 1;
                    mma16h(acc[mt][nt], ah[mt], bh[p][sel], bh[p][sel + 2]);
                }
        }
    }

    if (mode == 2) {
#pragma unroll
        for (int mt = 0; mt < 4; ++mt) {
            int m = m0 + wm + mt * 16 + g;
            int bi = m >> 11, n = m & 2047;
#pragma unroll
            for (int nt = 0; nt < 4; ++nt) {
                int o = n0 + wn + nt * 8 + 2 * tg;
                int h = o >> 6, d = o & 63;
                __half2 u0 = __floats2half2_rn(acc[mt][nt][0], acc[mt][nt][1]);
                __half2 u1 = __floats2half2_rn(acc[mt][nt][2], acc[mt][nt][3]);
                *(unsigned*)&Yh[(((size_t)(bi * H_ + h)) * 2048 + n) * D_ + d] = *(unsigned*)&u0;
                *(unsigned*)&Yh[(((size_t)(bi * H_ + h)) * 2048 + n + 8) * D_ + d] = *(unsigned*)&u1;
            }
        }
    } else {
#pragma unroll
        for (int mt = 0; mt < 4; ++mt) {
            int m = m0 + wm + mt * 16 + g;
#pragma unroll
            for (int nt = 0; nt < 4; ++nt) {
                int o = n0 + wn + nt * 8 + 2 * tg;
                float bx = bias[o], by = bias[o + 1];
                *(float2*)&Yf[(size_t)m * E_ + o] =
                    make_float2(acc[mt][nt][0] + bx, acc[mt][nt][1] + by);
                *(float2*)&Yf[(size_t)(m + 8) * E_ + o] =
                    make_float2(acc[mt][nt][2] + bx, acc[mt][nt][3] + by);
            }
        }
    }
}

// ---------------------------------------------------------------------------
// Attention: fp16 MMAs + fp16x2 softmax + ones-MMA row sums (round-11 core),
// key tiles of 128 (two 64-key halves per barrier), double-buffered cp.async.
// ---------------------------------------------------------------------------
#define AKST 18432u    // K stage bytes (128 rows * 144B)
#define ABST 36864u    // full stage (K+V)
#define ASM  (2 * 36864)

__global__ __launch_bounds__(256, 2) void attn_tc()
{
    extern __shared__ char sm[];
    const int tid = threadIdx.x, lane = tid & 31, warp = tid >> 5;
    const int g = lane >> 2, tg = lane & 3;
    const int bh = blockIdx.y, q0 = blockIdx.x * 128;

    const unsigned* Qg = (const unsigned*)(g_Q + ((size_t)bh * N_ + q0 + warp * 16) * D_);
    unsigned qa[4][4];
#pragma unroll
    for (int c = 0; c < 4; ++c) {
        qa[c][0] = Qg[g * 32 + c * 8 + tg];
        qa[c][1] = Qg[(g + 8) * 32 + c * 8 + tg];
        qa[c][2] = Qg[g * 32 + c * 8 + tg + 4];
        qa[c][3] = Qg[(g + 8) * 32 + c * 8 + tg + 4];
    }

    float o[8][4];
#pragma unroll
    for (int i = 0; i < 8; ++i)
#pragma unroll
        for (int j = 0; j < 4; ++j) o[i][j] = 0.f;
    float lsum[4] = {0.f, 0.f, 0.f, 0.f};

    const __half* Kh = g_K + (size_t)bh * M_ * D_;
    const __half* Vh = g_V + (size_t)bh * M_ * D_;
    const unsigned kb0 = smem_u32(sm);
    const int lrow = ((lane >> 3) & 1) * 8 + (lane & 7);
    const int lkh  = lane >> 4;

    const int srow = tid >> 1, si = tid & 1;
    auto issue = [&](int t, int b) {
        const __half* kr = Kh + (size_t)(t * 128 + srow) * D_ + si * 32;
        const __half* vr = Vh + (size_t)(t * 128 + srow) * D_ + si * 32;
        unsigned kd = kb0 + (unsigned)b * ABST + (unsigned)(srow * 144 + si * 64);
#pragma unroll
        for (int j = 0; j < 4; ++j) {
            cpa16(kd + j * 16,        kr + j * 8);
            cpa16(kd + AKST + j * 16, vr + j * 8);
        }
        cpacommit();
    };

    issue(0, 0);
    for (int t = 0; t < 16; ++t) {
        cpawait0();
        __syncthreads();
        if (t < 15) issue(t + 1, (t + 1) & 1);
        const unsigned bufo = (unsigned)(t & 1) * ABST;
        const unsigned kbb = kb0 + bufo;
        const unsigned vbb = kbb + AKST;

#pragma unroll
        for (int sub = 0; sub < 2; ++sub) {
            const unsigned rsub = (unsigned)(sub * 64 * 144);

            // S = Q K^T
            float s[8][4];
#pragma unroll
            for (int nt = 0; nt < 8; ++nt)
#pragma unroll
                for (int j = 0; j < 4; ++j) s[nt][j] = 0.f;
#pragma unroll
            for (int c = 0; c < 4; ++c) {
#pragma unroll
                for (int p = 0; p < 4; ++p) {
                    unsigned kb[4];
                    ldsm4(kb, kbb + rsub + (unsigned)((p * 16 + lrow) * 144 + c * 32 + lkh * 16));
                    mma16h(s[2 * p],     qa[c], kb[0], kb[2]);
                    mma16h(s[2 * p + 1], qa[c], kb[1], kb[3]);
                }
            }

            // exp in fp16x2 (results are PV A-frags); row sums via ones-MMA
            unsigned pa[4][4];
#pragma unroll
            for (int tt = 0; tt < 4; ++tt) {
                pa[tt][0] = h2ex2(packh(s[2 * tt][0],     s[2 * tt][1]));
                pa[tt][1] = h2ex2(packh(s[2 * tt][2],     s[2 * tt][3]));
                pa[tt][2] = h2ex2(packh(s[2 * tt + 1][0], s[2 * tt + 1][1]));
                pa[tt][3] = h2ex2(packh(s[2 * tt + 1][2], s[2 * tt + 1][3]));
                mma16h(lsum, pa[tt], ONESH2, ONESH2);
            }

            // O += P @ V
#pragma unroll
            for (int tt = 0; tt < 4; ++tt) {
#pragma unroll
                for (int dp = 0; dp < 4; ++dp) {
                    const int j = lane >> 3, rr = lane & 7;
                    int key = sub * 64 + tt * 16 + ((j & 1) << 3) + rr;
                    int dcol = dp * 16 + ((j >> 1) << 3);
                    unsigned vb[4];
                    ldsm4t(vb, kbb + AKST + (unsigned)(key * 144 + dcol * 2));
                    mma16h(o[2 * dp],     pa[tt], vb[0], vb[1]);
                    mma16h(o[2 * dp + 1], pa[tt], vb[2], vb[3]);
                }
            }
        }
    }

    const float inv0 = 1.f / lsum[0], inv1 = 1.f / lsum[2];
    const int bi = bh >> 4, h = bh & 15;
    const int n = q0 + warp * 16 + g;
#pragma unroll
    for (int dt = 0; dt < 8; ++dt) {
        int col = h * 64 + dt * 8 + 2 * tg;
        __half2 u0 = __floats2half2_rn(o[dt][0] * inv0, o[dt][1] * inv0);
        __half2 u1 = __floats2half2_rn(o[dt][2] * inv1, o[dt][3] * inv1);
        *(unsigned*)&g_AO[((size_t)bi * N_ + n) * E_ + col] = *(unsigned*)&u0;
        *(unsigned*)&g_AO[((size_t)bi * N_ + n + 8) * E_ + col] = *(unsigned*)&u1;
    }
}

// ---------------------------------------------------------------------------
extern "C" void kernel_launch(void* const* d_in, const int* in_sizes, int n_in,
                              void* d_out, int out_size)
{
    const float* x   = (const float*)d_in[0];
    const float* ctx = (const float*)d_in[1];
    const float* Wq  = (const float*)d_in[2];
    const float* Wk  = (const float*)d_in[3];
    const float* Wv  = (const float*)d_in[4];
    const float* Wo  = (const float*)d_in[5];
    const float* bo  = (const float*)d_in[6];
    float* out = (float*)d_out;

    __half *Qp, *Kp, *Vp, *Xh, *Ch, *AOp, *W4;
    cudaGetSymbolAddress((void**)&Qp,  g_Q);
    cudaGetSymbolAddress((void**)&Kp,  g_K);
    cudaGetSymbolAddress((void**)&Vp,  g_V);
    cudaGetSymbolAddress((void**)&Xh,  g_Xh);
    cudaGetSymbolAddress((void**)&Ch,  g_Ch);
    cudaGetSymbolAddress((void**)&AOp, g_AO);
    cudaGetSymbolAddress((void**)&W4,  g_W4);

    cudaFuncSetAttribute(gemm_h,  cudaFuncAttributeMaxDynamicSharedMemorySize, GSM);
    cudaFuncSetAttribute(attn_tc, cudaFuncAttributeMaxDynamicSharedMemorySize, ASM);

    const int n4x = R_ * E_ / 4;
    const float qs = 0.125f * 1.4426950408889634f;

    f2h2<<<2 * n4x / 256, 256>>>(x, ctx, Xh, Ch, n4x);
    f2hw<<<(E_ * E_) / 256, 256>>>(Wq, Wk, Wv, Wo, W4, qs);

    // fused Q/K/V projections (grid.z selects A, W, Y)
    gemm_h<<<dim3(8, 64, 3), 256, GSM>>>(Xh, Ch, W4, 0, nullptr, Qp, Kp, Vp, nullptr, 2);
    attn_tc<<<dim3(N_ / 128, B_ * H_), 256, ASM>>>();
    gemm_h<<<dim3(8, 64, 1), 256, GSM>>>(AOp, AOp, W4, 3, out, nullptr, nullptr, nullptr, bo, 1);
}

// round 15
// speedup vs baseline: 1.1340x; 1.1340x over previous
#include <cuda_runtime.h>
#include <cuda_fp16.h>
#include <cstdint>

#define B_  4
#define N_  2048
#define M_  2048
#define H_  16
#define D_  64
#define E_  1024
#define R_  8192   // B_*N_

// fp16 tensors
__device__ __half g_Q[(size_t)B_ * H_ * N_ * D_];   // pre-scaled (scale*log2e folded into Wq)
__device__ __half g_K[(size_t)B_ * H_ * M_ * D_];
__device__ __half g_V[(size_t)B_ * H_ * M_ * D_];
__device__ __half g_Xh[(size_t)R_ * E_];
__device__ __half g_Ch[(size_t)R_ * E_];
__device__ __half g_AO[(size_t)R_ * E_];
__device__ __half g_W4[(size_t)4 * E_ * E_];

// ---------------------------------------------------------------------------
// helpers
// ---------------------------------------------------------------------------
__device__ __forceinline__ void mma16h(float* d, const unsigned* a, unsigned b0, unsigned b1) {
    asm("mma.sync.aligned.m16n8k16.row.col.f32.f16.f16.f32 "
        "{%0,%1,%2,%3},{%4,%5,%6,%7},{%8,%9},{%0,%1,%2,%3};"
        : "+f"(d[0]), "+f"(d[1]), "+f"(d[2]), "+f"(d[3])
        : "r"(a[0]), "r"(a[1]), "r"(a[2]), "r"(a[3]), "r"(b0), "r"(b1));
}
__device__ __forceinline__ unsigned packh(float lo, float hi) {
    unsigned r; asm("cvt.rn.f16x2.f32 %0, %1, %2;" : "=r"(r) : "f"(hi), "f"(lo)); return r;
}
__device__ __forceinline__ unsigned h2ex2(unsigned x) {
    unsigned y; asm("ex2.approx.f16x2 %0, %1;" : "=r"(y) : "r"(x)); return y;
}
__device__ __forceinline__ void ldsm4(unsigned* r, unsigned addr) {
    asm volatile("ldmatrix.sync.aligned.m8n8.x4.shared.b16 {%0,%1,%2,%3}, [%4];"
                 : "=r"(r[0]), "=r"(r[1]), "=r"(r[2]), "=r"(r[3]) : "r"(addr));
}
__device__ __forceinline__ void ldsm4t(unsigned* r, unsigned addr) {
    asm volatile("ldmatrix.sync.aligned.m8n8.x4.trans.shared.b16 {%0,%1,%2,%3}, [%4];"
                 : "=r"(r[0]), "=r"(r[1]), "=r"(r[2]), "=r"(r[3]) : "r"(addr));
}
__device__ __forceinline__ void cpa16(unsigned dst, const void* src) {
    asm volatile("cp.async.cg.shared.global [%0], [%1], 16;" :: "r"(dst), "l"(src));
}
__device__ __forceinline__ void cpacommit() { asm volatile("cp.async.commit_group;"); }
__device__ __forceinline__ void cpawait0()  { asm volatile("cp.async.wait_group 0;"); }
__device__ __forceinline__ void cpawait1()  { asm volatile("cp.async.wait_group 1;"); }
__device__ __forceinline__ unsigned smem_u32(const void* p) {
    unsigned a;
    asm("{ .reg .u64 t; cvta.to.shared.u64 t, %1; cvt.u32.u64 %0, t; }" : "=r"(a) : "l"(p));
    return a;
}
#define ONESH2 0x3C003C00u   // fp16x2 {1.0, 1.0}

// ---------------------------------------------------------------------------
// Prep: fp32 -> fp16 converts (x+ctx fused; 4 weights fused)
// ---------------------------------------------------------------------------
__global__ __launch_bounds__(256) void f2h2(
    const float* __restrict__ x, const float* __restrict__ ctx,
    __half* __restrict__ Xh, __half* __restrict__ Ch, int n4)
{
    int i = blockIdx.x * 256 + threadIdx.x;
    const float* s; __half* d; int j;
    if (i < n4) { s = x; d = Xh; j = i; } else { s = ctx; d = Ch; j = i - n4; }
    float4 v = ((const float4*)s)[j];
    __half2 a = __floats2half2_rn(v.x, v.y);
    __half2 b = __floats2half2_rn(v.z, v.w);
    uint2 u; u.x = *(unsigned*)&a; u.y = *(unsigned*)&b;
    *(uint2*)&d[(size_t)j * 4] = u;
}
__global__ __launch_bounds__(256) void f2hw(
    const float* __restrict__ w0, const float* __restrict__ w1,
    const float* __restrict__ w2, const float* __restrict__ w3,
    __half* __restrict__ dst, float qs)
{
    int i = blockIdx.x * 256 + threadIdx.x;
    const int per = E_ * E_ / 4;
    int s = i / per, j = i - s * per;
    const float* src = (s == 0) ? w0 : (s == 1) ? w1 : (s == 2) ? w2 : w3;
    float scale = (s == 0) ? qs : 1.f;
    float4 v = ((const float4*)src)[j];
    __half2 a = __floats2half2_rn(v.x * scale, v.y * scale);
    __half2 b = __floats2half2_rn(v.z * scale, v.w * scale);
    uint2 u; u.x = *(unsigned*)&a; u.y = *(unsigned*)&b;
    *(uint2*)&dst[(size_t)i * 4] = u;
}

// ---------------------------------------------------------------------------
// fp16 GEMM (round-11 proven body): Y = A (R x 1024) @ W^T, fp32 accumulate.
// Block 128x128, 8 warps, warp tile 64x32, K-chunks of 16, 3-stage cp.async,
// 48B row stride (conflict-free ldmatrix). grid.z selects {A, W, Y} for the
// fused Q/K/V projection launch. mode 1: fp32 [r][o] + bias.
// ---------------------------------------------------------------------------
__global__ __launch_bounds__(256) void gemm_h(
    const __half* __restrict__ A0, const __half* __restrict__ A1,
    const __half* __restrict__ Wb, int wofs,
    float* __restrict__ Yf, __half* __restrict__ Y0, __half* __restrict__ Y1,
    __half* __restrict__ Y2, const float* __restrict__ bias, int mode)
{
    __shared__ unsigned As[3][1536], Bs[3][1536];   // 128 rows * 12 u32 (48B)

    const int z = blockIdx.z;
    const __half* A = (z == 0) ? A0 : A1;
    const __half* W = Wb + (size_t)(wofs + z) * E_ * E_;
    __half* Yh = (z == 0) ? Y0 : (z == 1) ? Y1 : Y2;

    const int tid = threadIdx.x, lane = tid & 31, warp = tid >> 5;
    const int g = lane >> 2, tg = lane & 3;
    const int wm = (warp >> 2) * 64, wn = (warp & 3) * 32;
    const int m0 = blockIdx.y * 128, n0 = blockIdx.x * 128;

    const unsigned asB = smem_u32(As);
    const unsigned bsB = smem_u32(Bs);
    const int lrow = ((lane >> 3) & 1) * 8 + (lane & 7);
    const int lkh  = lane >> 4;
    const unsigned aoff = (unsigned)((wm + lrow) * 48 + lkh * 16);
    const unsigned boff = (unsigned)((wn + lrow) * 48 + lkh * 16);

    const int crow = tid >> 1, chalf = tid & 1;
    const __half* Asrc = A + (size_t)(m0 + crow) * E_ + chalf * 8;
    const __half* Bsrc = W + (size_t)(n0 + crow) * E_ + chalf * 8;
    const unsigned cdst = (unsigned)(crow * 48 + chalf * 16);

    auto issue = [&](int c) {
        const unsigned d = cdst + (unsigned)(c % 3) * 6144u;
        cpa16(asB + d, Asrc + c * 16);
        cpa16(bsB + d, Bsrc + c * 16);
        cpacommit();
    };

    float acc[4][4][4];
#pragma unroll
    for (int i = 0; i < 4; ++i)
#pragma unroll
        for (int j = 0; j < 4; ++j)
#pragma unroll
            for (int k = 0; k < 4; ++k) acc[i][j][k] = 0.f;

    issue(0);
    issue(1);
    for (int c = 0; c < 64; ++c) {
        if (c < 63) cpawait1(); else cpawait0();
        __syncthreads();
        if (c < 62) issue(c + 2);
        const unsigned bufo = (unsigned)(c % 3) * 6144u;

        unsigned ah[4][4], bh[2][4];
#pragma unroll
        for (int mt = 0; mt < 4; ++mt)
            ldsm4(ah[mt], asB + bufo + aoff + (unsigned)mt * 768u);
#pragma unroll
        for (int p = 0; p < 2; ++p)
            ldsm4(bh[p], bsB + bufo + boff + (unsigned)p * 768u);
#pragma unroll
        for (int mt = 0; mt < 4; ++mt)
#pragma unroll
            for (int nt = 0; nt < 4; ++nt) {
                const int p = nt >> 1, sel = nt & 1;
                mma16h(acc[mt][nt], ah[mt], bh[p][sel], bh[p][sel + 2]);
            }
    }

    if (mode == 2) {
#pragma unroll
        for (int mt = 0; mt < 4; ++mt) {
            int m = m0 + wm + mt * 16 + g;
            int bi = m >> 11, n = m & 2047;
#pragma unroll
            for (int nt = 0; nt < 4; ++nt) {
                int o = n0 + wn + nt * 8 + 2 * tg;
                int h = o >> 6, d = o & 63;
                __half2 u0 = __floats2half2_rn(acc[mt][nt][0], acc[mt][nt][1]);
                __half2 u1 = __floats2half2_rn(acc[mt][nt][2], acc[mt][nt][3]);
                *(unsigned*)&Yh[(((size_t)(bi * H_ + h)) * 2048 + n) * D_ + d] = *(unsigned*)&u0;
                *(unsigned*)&Yh[(((size_t)(bi * H_ + h)) * 2048 + n + 8) * D_ + d] = *(unsigned*)&u1;
            }
        }
    } else {
#pragma unroll
        for (int mt = 0; mt < 4; ++mt) {
            int m = m0 + wm + mt * 16 + g;
#pragma unroll
            for (int nt = 0; nt < 4; ++nt) {
                int o = n0 + wn + nt * 8 + 2 * tg;
                float bx = bias[o], by = bias[o + 1];
                *(float2*)&Yf[(size_t)m * E_ + o] =
                    make_float2(acc[mt][nt][0] + bx, acc[mt][nt][1] + by);
                *(float2*)&Yf[(size_t)(m + 8) * E_ + o] =
                    make_float2(acc[mt][nt][2] + bx, acc[mt][nt][3] + by);
            }
        }
    }
}

// ---------------------------------------------------------------------------
// Attention (round-11 proven): fp16 MMAs + fp16x2 softmax + ones-MMA row
// sums; 64-key tiles, double-buffered cp.async.
// ---------------------------------------------------------------------------
__global__ __launch_bounds__(256, 2) void attn_tc()
{
    __shared__ unsigned Ks2[2][64 * 36];   // fp16 pairs, row stride 144B
    __shared__ unsigned Vs2[2][64 * 36];

    const int tid = threadIdx.x, lane = tid & 31, warp = tid >> 5;
    const int g = lane >> 2, tg = lane & 3;
    const int bh = blockIdx.y, q0 = blockIdx.x * 128;

    const unsigned* Qg = (const unsigned*)(g_Q + ((size_t)bh * N_ + q0 + warp * 16) * D_);
    unsigned qa[4][4];
#pragma unroll
    for (int c = 0; c < 4; ++c) {
        qa[c][0] = Qg[g * 32 + c * 8 + tg];
        qa[c][1] = Qg[(g + 8) * 32 + c * 8 + tg];
        qa[c][2] = Qg[g * 32 + c * 8 + tg + 4];
        qa[c][3] = Qg[(g + 8) * 32 + c * 8 + tg + 4];
    }

    float o[8][4];
#pragma unroll
    for (int i = 0; i < 8; ++i)
#pragma unroll
        for (int j = 0; j < 4; ++j) o[i][j] = 0.f;
    float lsum[4] = {0.f, 0.f, 0.f, 0.f};   // row-sum accumulator (ones-MMA)

    const __half* Kh = g_K + (size_t)bh * M_ * D_;
    const __half* Vh = g_V + (size_t)bh * M_ * D_;
    const unsigned kb0 = smem_u32(Ks2);
    const unsigned vb0 = smem_u32(Vs2);
    const int lrow = ((lane >> 3) & 1) * 8 + (lane & 7);
    const int lkh  = lane >> 4;

    const int srow = tid >> 2, si = tid & 3;
    auto issue = [&](int t, int b) {
        const __half* kr = Kh + (size_t)(t * 64 + srow) * D_;
        const __half* vr = Vh + (size_t)(t * 64 + srow) * D_;
        unsigned kd = kb0 + (unsigned)b * 9216u + (unsigned)(srow * 144 + si * 16);
        unsigned vd = vb0 + (unsigned)b * 9216u + (unsigned)(srow * 144 + si * 16);
        cpa16(kd,      kr + si * 8);
        cpa16(kd + 64, kr + si * 8 + 32);
        cpa16(vd,      vr + si * 8);
        cpa16(vd + 64, vr + si * 8 + 32);
        cpacommit();
    };

    issue(0, 0);
    for (int t = 0; t < 32; ++t) {
        cpawait0();
        __syncthreads();
        if (t < 31) issue(t + 1, (t + 1) & 1);
        const unsigned bufo = (unsigned)(t & 1) * 9216u;

        // S = Q K^T (fp16 MMA, fp32 accum); scale*log2e folded into Q
        float s[8][4];
#pragma unroll
        for (int nt = 0; nt < 8; ++nt)
#pragma unroll
            for (int j = 0; j < 4; ++j) s[nt][j] = 0.f;
#pragma unroll
        for (int c = 0; c < 4; ++c) {
#pragma unroll
            for (int p = 0; p < 4; ++p) {
                unsigned kb[4];
                ldsm4(kb, kb0 + bufo + (unsigned)((p * 16 + lrow) * 144 + c * 32 + lkh * 16));
                mma16h(s[2 * p],     qa[c], kb[0], kb[2]);
                mma16h(s[2 * p + 1], qa[c], kb[1], kb[3]);
            }
        }

        // exp in fp16x2 (results are PV A-frags); row sums via ones-MMA
        unsigned pa[4][4];
#pragma unroll
        for (int tt = 0; tt < 4; ++tt) {
            pa[tt][0] = h2ex2(packh(s[2 * tt][0],     s[2 * tt][1]));
            pa[tt][1] = h2ex2(packh(s[2 * tt][2],     s[2 * tt][3]));
            pa[tt][2] = h2ex2(packh(s[2 * tt + 1][0], s[2 * tt + 1][1]));
            pa[tt][3] = h2ex2(packh(s[2 * tt + 1][2], s[2 * tt + 1][3]));
            mma16h(lsum, pa[tt], ONESH2, ONESH2);
        }

        // O += P @ V
#pragma unroll
        for (int tt = 0; tt < 4; ++tt) {
#pragma unroll
            for (int dp = 0; dp < 4; ++dp) {
                const int j = lane >> 3, rr = lane & 7;
                int key = tt * 16 + ((j & 1) << 3) + rr;
                int dcol = dp * 16 + ((j >> 1) << 3);
                unsigned vb[4];
                ldsm4t(vb, vb0 + bufo + (unsigned)(key * 144 + dcol * 2));
                mma16h(o[2 * dp],     pa[tt], vb[0], vb[1]);
                mma16h(o[2 * dp + 1], pa[tt], vb[2], vb[3]);
            }
        }
    }

    const float inv0 = 1.f / lsum[0], inv1 = 1.f / lsum[2];
    const int bi = bh >> 4, h = bh & 15;
    const int n = q0 + warp * 16 + g;
#pragma unroll
    for (int dt = 0; dt < 8; ++dt) {
        int col = h * 64 + dt * 8 + 2 * tg;
        __half2 u0 = __floats2half2_rn(o[dt][0] * inv0, o[dt][1] * inv0);
        __half2 u1 = __floats2half2_rn(o[dt][2] * inv1, o[dt][3] * inv1);
        *(unsigned*)&g_AO[((size_t)bi * N_ + n) * E_ + col] = *(unsigned*)&u0;
        *(unsigned*)&g_AO[((size_t)bi * N_ + n + 8) * E_ + col] = *(unsigned*)&u1;
    }
}

// ---------------------------------------------------------------------------
extern "C" void kernel_launch(void* const* d_in, const int* in_sizes, int n_in,
                              void* d_out, int out_size)
{
    const float* x   = (const float*)d_in[0];
    const float* ctx = (const float*)d_in[1];
    const float* Wq  = (const float*)d_in[2];
    const float* Wk  = (const float*)d_in[3];
    const float* Wv  = (const float*)d_in[4];
    const float* Wo  = (const float*)d_in[5];
    const float* bo  = (const float*)d_in[6];
    float* out = (float*)d_out;

    __half *Qp, *Kp, *Vp, *Xh, *Ch, *AOp, *W4;
    cudaGetSymbolAddress((void**)&Qp,  g_Q);
    cudaGetSymbolAddress((void**)&Kp,  g_K);
    cudaGetSymbolAddress((void**)&Vp,  g_V);
    cudaGetSymbolAddress((void**)&Xh,  g_Xh);
    cudaGetSymbolAddress((void**)&Ch,  g_Ch);
    cudaGetSymbolAddress((void**)&AOp, g_AO);
    cudaGetSymbolAddress((void**)&W4,  g_W4);

    const int n4x = R_ * E_ / 4;
    const float qs = 0.125f * 1.4426950408889634f;

    f2h2<<<2 * n4x / 256, 256>>>(x, ctx, Xh, Ch, n4x);
    f2hw<<<(E_ * E_) / 256, 256>>>(Wq, Wk, Wv, Wo, W4, qs);

    // fused Q/K/V projections (grid.z selects A, W, Y); round-11 GEMM body
    gemm_h<<<dim3(8, 64, 3), 256>>>(Xh, Ch, W4, 0, nullptr, Qp, Kp, Vp, nullptr, 2);
    attn_tc<<<dim3(N_ / 128, B_ * H_), 256>>>();
    gemm_h<<<dim3(8, 64, 1), 256>>>(AOp, AOp, W4, 3, out, nullptr, nullptr, nullptr, bo, 1);
}